// round 3
// baseline (speedup 1.0000x reference)
#include <cuda_runtime.h>
#include <cstdint>
#include <cstddef>

#define LORA_SCALING 4.0f   // alpha/rank = 32/8

// Scratch for T = (x @ lora_A) * scaling.  8MB, far above the 8192*8 needed.
__device__ float g_T[1 << 21];

// ---------------------------------------------------------------------------
// Kernel 1: T[M,R] = (x[M,K] @ A[K,R]) * scale
// One warp per row; A transposed into SMEM once per block.
// ---------------------------------------------------------------------------
template <int R>
__global__ void lora_xa_kernel(const float* __restrict__ x,
                               const float* __restrict__ A,
                               float* __restrict__ T,
                               int M, int K, float scale) {
    extern __shared__ float As[];  // [R][K]
    int tid = threadIdx.x;
    for (int i = tid; i < K * R; i += blockDim.x) {
        int k = i / R, r = i - k * R;
        As[r * K + k] = A[i];
    }
    __syncthreads();

    int w = tid >> 5, lane = tid & 31;
    int row = blockIdx.x * (blockDim.x >> 5) + w;
    if (row >= M) return;

    const float* xr = x + (size_t)row * K;
    float acc[R];
#pragma unroll
    for (int r = 0; r < R; r++) acc[r] = 0.f;

    for (int k = lane; k < K; k += 32) {
        float xv = xr[k];
#pragma unroll
        for (int r = 0; r < R; r++) acc[r] += xv * As[r * K + k];
    }
#pragma unroll
    for (int r = 0; r < R; r++) {
#pragma unroll
        for (int off = 16; off; off >>= 1)
            acc[r] += __shfl_down_sync(0xffffffffu, acc[r], off);
    }
    if (lane == 0) {
#pragma unroll
        for (int r = 0; r < R; r++) T[(size_t)row * R + r] = acc[r] * scale;
    }
}

// Generic fallback for uncommon R (runtime bound, capped at 32).
__global__ void lora_xa_generic(const float* __restrict__ x,
                                const float* __restrict__ A,
                                float* __restrict__ T,
                                int M, int K, int R, float scale) {
    extern __shared__ float As[];
    int tid = threadIdx.x;
    for (int i = tid; i < K * R; i += blockDim.x) {
        int k = i / R, r = i - k * R;
        As[r * K + k] = A[i];
    }
    __syncthreads();
    int w = tid >> 5, lane = tid & 31;
    int row = blockIdx.x * (blockDim.x >> 5) + w;
    if (row >= M) return;
    const float* xr = x + (size_t)row * K;
    float acc[32];
    for (int r = 0; r < 32; r++) acc[r] = 0.f;
    for (int k = lane; k < K; k += 32) {
        float xv = xr[k];
        for (int r = 0; r < R; r++) acc[r] += xv * As[r * K + k];
    }
    for (int r = 0; r < R; r++) {
        for (int off = 16; off; off >>= 1)
            acc[r] += __shfl_down_sync(0xffffffffu, acc[r], off);
        if (lane == 0) T[(size_t)row * R + r] = acc[r] * scale;
    }
}

// ---------------------------------------------------------------------------
// Kernel 2: out[M,N] = x[M,K] @ W[K,N] + T[M,R] @ loraB[R,N] + bias[N]
// TF32 mma.sync m16n8k8, BM=128 BN=128 BK=32, cp.async double buffering.
// LoRA term implemented as one extra zero-padded K-tile.
// ---------------------------------------------------------------------------
#define BM 128
#define BN 128
#define BK 32
#define ASTRIDE 36    // 128x36 floats per A buffer (pad: conflict-free frag loads)
#define BSTRIDE 136   // 32x136 floats per B buffer

__device__ __forceinline__ uint32_t f2tf32(float f) {
    uint32_t u;
    asm("cvt.rna.tf32.f32 %0, %1;" : "=r"(u) : "f"(f));
    return u;
}

__device__ __forceinline__ void mma_tf32(float* c, const uint32_t* a, const uint32_t* b) {
    asm volatile(
        "mma.sync.aligned.m16n8k8.row.col.f32.tf32.tf32.f32 "
        "{%0,%1,%2,%3}, {%4,%5,%6,%7}, {%8,%9}, {%0,%1,%2,%3};"
        : "+f"(c[0]), "+f"(c[1]), "+f"(c[2]), "+f"(c[3])
        : "r"(a[0]), "r"(a[1]), "r"(a[2]), "r"(a[3]), "r"(b[0]), "r"(b[1]));
}

__device__ __forceinline__ void cp_async16(uint32_t dst, const void* src, int src_bytes) {
    asm volatile("cp.async.cg.shared.global [%0], [%1], 16, %2;\n"
                 :: "r"(dst), "l"(src), "r"(src_bytes));
}

__global__ __launch_bounds__(256, 2)
void lora_gemm_kernel(const float* __restrict__ x, const float* __restrict__ W,
                      const float* __restrict__ bias, const float* __restrict__ T,
                      const float* __restrict__ loraB, float* __restrict__ out,
                      int M, int N, int K, int R) {
    extern __shared__ float smem[];
    float* As = smem;                          // [2][BM][ASTRIDE]
    float* Bs = smem + 2 * BM * ASTRIDE;       // [2][BK][BSTRIDE]

    const int tid = threadIdx.x;
    const int m0 = blockIdx.y * BM;
    const int n0 = blockIdx.x * BN;
    const int KT = K / BK;        // full K tiles
    const int NT = KT + 1;        // + LoRA pseudo tile

    // Per-thread load coordinates (4 x 16B each for A and B tiles)
    int ar[4], ac[4], bk[4], bc[4];
#pragma unroll
    for (int i = 0; i < 4; i++) {
        int idx = tid + i * 256;
        ar[i] = idx >> 3;  ac[i] = (idx & 7) * 4;
        bk[i] = idx >> 5;  bc[i] = (idx & 31) * 4;
    }

    auto prefetch = [&](int kt, int buf) {
        float* Asb = As + buf * (BM * ASTRIDE);
        float* Bsb = Bs + buf * (BK * BSTRIDE);
        bool pseudo = (kt == KT);
#pragma unroll
        for (int i = 0; i < 4; i++) {
            uint32_t dst = (uint32_t)__cvta_generic_to_shared(Asb + ar[i] * ASTRIDE + ac[i]);
            int grow = m0 + ar[i];
            const float* src;
            int sz;
            if (!pseudo) {
                src = x + (size_t)grow * K + kt * BK + ac[i];
                sz = (grow < M) ? 16 : 0;
            } else {
                src = T + (size_t)grow * R + ac[i];
                sz = (grow < M && ac[i] + 4 <= R) ? 16 : 0;
            }
            cp_async16(dst, src, sz);
        }
#pragma unroll
        for (int i = 0; i < 4; i++) {
            uint32_t dst = (uint32_t)__cvta_generic_to_shared(Bsb + bk[i] * BSTRIDE + bc[i]);
            int gcol = n0 + bc[i];
            bool colok = (gcol + 4 <= N);
            const float* src;
            int sz;
            if (!pseudo) {
                src = W + (size_t)(kt * BK + bk[i]) * N + gcol;
                sz = colok ? 16 : 0;
            } else {
                src = loraB + (size_t)bk[i] * N + gcol;
                sz = (colok && bk[i] < R) ? 16 : 0;
            }
            cp_async16(dst, src, sz);
        }
        asm volatile("cp.async.commit_group;\n" ::: "memory");
    };

    // Warp layout: 8 warps = 4(m) x 2(n); warp tile 32 x 64
    const int w = tid >> 5, lane = tid & 31;
    const int wm = (w >> 1) * 32;
    const int wn = (w & 1) * 64;
    const int g = lane >> 2, t4 = lane & 3;

    float acc[2][8][4];
#pragma unroll
    for (int mi = 0; mi < 2; mi++)
#pragma unroll
        for (int ni = 0; ni < 8; ni++)
#pragma unroll
            for (int e = 0; e < 4; e++) acc[mi][ni][e] = 0.f;

    prefetch(0, 0);
    int buf = 0;
    for (int kt = 0; kt < NT; kt++) {
        asm volatile("cp.async.wait_group 0;\n" ::: "memory");
        __syncthreads();
        if (kt + 1 < NT) prefetch(kt + 1, buf ^ 1);

        const float* Asb = As + buf * (BM * ASTRIDE);
        const float* Bsb = Bs + buf * (BK * BSTRIDE);
#pragma unroll
        for (int ks = 0; ks < 4; ks++) {
            const int kk = ks * 8;
            uint32_t afr[2][4], bfr[8][2];
#pragma unroll
            for (int mi = 0; mi < 2; mi++) {
                int r0 = wm + mi * 16 + g;
                afr[mi][0] = f2tf32(Asb[r0 * ASTRIDE + kk + t4]);
                afr[mi][1] = f2tf32(Asb[(r0 + 8) * ASTRIDE + kk + t4]);
                afr[mi][2] = f2tf32(Asb[r0 * ASTRIDE + kk + t4 + 4]);
                afr[mi][3] = f2tf32(Asb[(r0 + 8) * ASTRIDE + kk + t4 + 4]);
            }
#pragma unroll
            for (int ni = 0; ni < 8; ni++) {
                int c = wn + ni * 8 + g;
                bfr[ni][0] = f2tf32(Bsb[(kk + t4) * BSTRIDE + c]);
                bfr[ni][1] = f2tf32(Bsb[(kk + t4 + 4) * BSTRIDE + c]);
            }
#pragma unroll
            for (int mi = 0; mi < 2; mi++)
#pragma unroll
                for (int ni = 0; ni < 8; ni++)
                    mma_tf32(acc[mi][ni], afr[mi], bfr[ni]);
        }
        buf ^= 1;
    }

    // Epilogue: add bias, store float2 pairs
#pragma unroll
    for (int mi = 0; mi < 2; mi++) {
        int r0 = m0 + wm + mi * 16 + g;
        int r1 = r0 + 8;
#pragma unroll
        for (int ni = 0; ni < 8; ni++) {
            int c = n0 + wn + ni * 8 + 2 * t4;
            if (c + 1 < N) {
                float bv0 = __ldg(bias + c);
                float bv1 = __ldg(bias + c + 1);
                if (r0 < M) {
                    float2 v = make_float2(acc[mi][ni][0] + bv0, acc[mi][ni][1] + bv1);
                    *reinterpret_cast<float2*>(out + (size_t)r0 * N + c) = v;
                }
                if (r1 < M) {
                    float2 v = make_float2(acc[mi][ni][2] + bv0, acc[mi][ni][3] + bv1);
                    *reinterpret_cast<float2*>(out + (size_t)r1 * N + c) = v;
                }
            }
        }
    }
}

// ---------------------------------------------------------------------------
extern "C" void kernel_launch(void* const* d_in, const int* in_sizes, int n_in,
                              void* d_out, int out_size) {
    const float* x  = (const float*)d_in[0];
    const float* W  = (const float*)d_in[1];
    const float* b  = (const float*)d_in[2];
    const float* lA = (const float*)d_in[3];
    const float* lB = (const float*)d_in[4];
    float* out = (float*)d_out;

    const int Dout = in_sizes[2];
    const int Din  = in_sizes[1] / Dout;
    const int R    = in_sizes[3] / Din;
    const int M    = in_sizes[0] / Din;
    const int N    = Dout;
    const int K    = Din;

    float* T = nullptr;
    cudaGetSymbolAddress((void**)&T, g_T);

    // ---- Kernel 1: T = (x @ A) * scaling ----
    {
        const int threads = 512;                 // 16 warps = 16 rows/block
        const int rows_per_blk = threads / 32;
        const int grid = (M + rows_per_blk - 1) / rows_per_blk;
        const size_t smem = (size_t)R * K * sizeof(float);
        if (R == 8) {
            cudaFuncSetAttribute(lora_xa_kernel<8>,
                                 cudaFuncAttributeMaxDynamicSharedMemorySize, (int)smem);
            lora_xa_kernel<8><<<grid, threads, smem>>>(x, lA, T, M, K, LORA_SCALING);
        } else if (R == 16) {
            cudaFuncSetAttribute(lora_xa_kernel<16>,
                                 cudaFuncAttributeMaxDynamicSharedMemorySize, (int)smem);
            lora_xa_kernel<16><<<grid, threads, smem>>>(x, lA, T, M, K, LORA_SCALING);
        } else if (R == 4) {
            cudaFuncSetAttribute(lora_xa_kernel<4>,
                                 cudaFuncAttributeMaxDynamicSharedMemorySize, (int)smem);
            lora_xa_kernel<4><<<grid, threads, smem>>>(x, lA, T, M, K, LORA_SCALING);
        } else {
            cudaFuncSetAttribute(lora_xa_generic,
                                 cudaFuncAttributeMaxDynamicSharedMemorySize, (int)smem);
            lora_xa_generic<<<grid, threads, smem>>>(x, lA, T, M, K, R, LORA_SCALING);
        }
    }

    // ---- Kernel 2: fused GEMM + LoRA pseudo-tile + bias ----
    {
        const int smem = (2 * BM * ASTRIDE + 2 * BK * BSTRIDE) * (int)sizeof(float); // 71680
        cudaFuncSetAttribute(lora_gemm_kernel,
                             cudaFuncAttributeMaxDynamicSharedMemorySize, smem);
        dim3 grid((N + BN - 1) / BN, (M + BM - 1) / BM);
        lora_gemm_kernel<<<grid, 256, smem>>>(x, W, b, T, lB, out, M, N, K, R);
    }
}